// round 1
// baseline (speedup 1.0000x reference)
#include <cuda_runtime.h>
#include <cstdint>
#include <math.h>

// StructPool: B=8, N=2048, D=64, K=16, 5 mean-field iterations.
//
// Restructured math (identical results up to f32 rounding):
//   Xp[b,j,k]   = mean over 4 of X row (pool commutes with A@X)
//   Uraw        = A @ Xp                      (pass 1 over A)
//   U           = tanh(Uraw / rowsum(Uraw))
//   norm_i      = x_i . colsum_b - ||x_i||^2
//   per iter:   s = softmax(q); G = X^T s  [64x16/batch]
//               out0_i = (x_i . G - ||x_i||^2 s_i) / norm_i
//               q = U - out0 @ (w_filter @ w_compat)
//   L = softmax(q)
//   t = A @ L                                 (pass 2 over A)
//   X_out = L^T X ; A_out = L^T t

#define BB 8
#define NN 2048
#define DD 64
#define KK 16
#define ITERS 5
#define GCH 32          // row chunks of 64 for partial reductions

// ---- scratch (device globals; no allocation allowed) ----
__device__ float g_Xp[BB*NN*KK];
__device__ float g_normsq[BB*NN];
__device__ float g_norminv[BB*NN];
__device__ float g_colsum[BB*DD];
__device__ float g_M[KK*KK];
__device__ float g_U[BB*NN*KK];
__device__ float g_q[BB*NN*KK];
__device__ float g_s[BB*NN*KK];      // holds s during iters, L at the end
__device__ float g_t[BB*NN*KK];
__device__ float g_Gpart[BB*GCH*DD*KK];
__device__ float g_XOpart[BB*GCH*KK*DD];

// ---- packed f32x2 helpers (Blackwell) ----
__device__ __forceinline__ unsigned long long pack2(float a) {
    unsigned long long r;
    asm("mov.b64 %0, {%1, %1};" : "=l"(r) : "f"(a));
    return r;
}
__device__ __forceinline__ unsigned long long fma2(unsigned long long a,
                                                   unsigned long long b,
                                                   unsigned long long c) {
    unsigned long long d;
    asm("fma.rn.f32x2 %0, %1, %2, %3;" : "=l"(d) : "l"(a), "l"(b), "l"(c));
    return d;
}

// ---- 1. per-row preprocess: Xp (adaptive pool) + ||x||^2 ----
__global__ void prep_kernel(const float* __restrict__ X) {
    int row = blockIdx.x * blockDim.x + threadIdx.x;   // 0 .. B*N-1
    const float4* xr = reinterpret_cast<const float4*>(X + (size_t)row * DD);
    float ns = 0.f;
    float* xp = g_Xp + (size_t)row * KK;
#pragma unroll
    for (int p = 0; p < 16; p++) {
        float4 v = xr[p];
        xp[p] = (v.x + v.y + v.z + v.w) * 0.25f;
        ns += v.x*v.x + v.y*v.y + v.z*v.z + v.w*v.w;
    }
    g_normsq[row] = ns;
}

// ---- 2. colsum per batch + M = w_filter @ w_compat ----
__global__ void colsumM_kernel(const float* __restrict__ X,
                               const float* __restrict__ wf,
                               const float* __restrict__ wc) {
    if (blockIdx.x < BB) {
        int b = blockIdx.x;
        int d = threadIdx.x;
        if (d < DD) {
            float s = 0.f;
            const float* base = X + ((size_t)b * NN) * DD + d;
            for (int i = 0; i < NN; i++) s += base[(size_t)i * DD];
            g_colsum[b * DD + d] = s;
        }
    } else {
        int t = threadIdx.x;
        if (t < KK * KK) {
            int k1 = t / KK, k2 = t % KK;
            float s = 0.f;
#pragma unroll
            for (int k = 0; k < KK; k++) s += wf[k1*KK + k] * wc[k*KK + k2];
            g_M[t] = s;
        }
    }
}

// ---- 3. norm_i = x_i . colsum - ||x_i||^2 ; store reciprocal ----
__global__ void norm_kernel(const float* __restrict__ X) {
    int row = blockIdx.x * blockDim.x + threadIdx.x;
    int b = row / NN;
    const float* xr = X + (size_t)row * DD;
    const float* cs = g_colsum + b * DD;
    float dot = 0.f;
#pragma unroll
    for (int d = 0; d < DD; d++) dot += xr[d] * cs[d];
    g_norminv[row] = 1.0f / (dot - g_normsq[row]);
}

// ---- 4/8. big pass over A: R = A @ V, V in {Xp, L}, 16 cols ----
// Uses A symmetry: read A[b][j][i] with i = thread (coalesced), j = loop.
// MODE 0: V = Xp, epilogue U = tanh(r / sum(r)), also init q = U.
// MODE 1: V = L (in g_s), write g_t.
template <int MODE>
__global__ void __launch_bounds__(128) bigpass_kernel(const float* __restrict__ A) {
    __shared__ float sV[256 * KK];                 // 16 KB chunk of V
    int b = blockIdx.y;
    int i = blockIdx.x * 128 + threadIdx.x;        // this thread's output row
    const float* V = (MODE == 0) ? g_Xp : g_s;
    const float* Ab = A + (size_t)b * NN * NN;

    unsigned long long acc[8];
#pragma unroll
    for (int p = 0; p < 8; p++) acc[p] = 0ull;

    for (int c = 0; c < NN; c += 256) {
        const float4* src = reinterpret_cast<const float4*>(V + ((size_t)b * NN + c) * KK);
        float4* dst = reinterpret_cast<float4*>(sV);
        for (int e = threadIdx.x; e < 256 * KK / 4; e += 128) dst[e] = src[e];
        __syncthreads();
#pragma unroll 4
        for (int j = 0; j < 256; j++) {
            float a = Ab[(size_t)(c + j) * NN + i];
            unsigned long long aa = pack2(a);
            const unsigned long long* vp =
                reinterpret_cast<const unsigned long long*>(sV + j * KK);
#pragma unroll
            for (int p = 0; p < 8; p++) acc[p] = fma2(aa, vp[p], acc[p]);
        }
        __syncthreads();
    }

    float r[KK];
#pragma unroll
    for (int p = 0; p < 8; p++) {
        r[2*p]   = __uint_as_float((unsigned)(acc[p] & 0xffffffffu));
        r[2*p+1] = __uint_as_float((unsigned)(acc[p] >> 32));
    }

    size_t off = ((size_t)b * NN + i) * KK;
    if (MODE == 0) {
        float sum = 0.f;
#pragma unroll
        for (int k = 0; k < KK; k++) sum += r[k];
        float inv = 1.0f / sum;
        float* U = g_U + off;
        float* q = g_q + off;
#pragma unroll
        for (int k = 0; k < KK; k++) {
            float u = tanhf(r[k] * inv);
            U[k] = u; q[k] = u;
        }
    } else {
        float* t = g_t + off;
#pragma unroll
        for (int k = 0; k < KK; k++) t[k] = r[k];
    }
}

// ---- 5. per-iteration phase A: s = softmax(q), partial G (or partial X_out) ----
// OUTMODE 0: Gpart[b][ch][d*16+k] += X[i][d]*s[i][k]
// OUTMODE 1: XOpart[b][ch][k*64+d] += s[i][k]*X[i][d]   (here s = L)
template <int OUTMODE>
__global__ void __launch_bounds__(256) iterA_kernel(const float* __restrict__ X) {
    __shared__ float ss[64 * KK];
    int b = blockIdx.y, ch = blockIdx.x, tid = threadIdx.x;
    int rb = ch * 64;

    if (tid < 64) {
        size_t gr = (size_t)b * NN + rb + tid;
        const float* qr = g_q + gr * KK;
        float v[KK];
        float m = -1e30f;
#pragma unroll
        for (int k = 0; k < KK; k++) { v[k] = qr[k]; m = fmaxf(m, v[k]); }
        float sum = 0.f;
#pragma unroll
        for (int k = 0; k < KK; k++) { v[k] = expf(v[k] - m); sum += v[k]; }
        float inv = 1.0f / sum;
        float* sr = g_s + gr * KK;
#pragma unroll
        for (int k = 0; k < KK; k++) {
            float sv = v[k] * inv;
            ss[tid * KK + k] = sv;
            sr[k] = sv;
        }
    }
    __syncthreads();

    int d = tid & 63, kb = (tid >> 6) * 4;
    float a0 = 0, a1 = 0, a2 = 0, a3 = 0;
    const float* Xb = X + ((size_t)b * NN + rb) * DD + d;
#pragma unroll 4
    for (int i2 = 0; i2 < 64; i2++) {
        float x = Xb[(size_t)i2 * DD];
        const float* s4 = &ss[i2 * KK + kb];
        a0 += x * s4[0]; a1 += x * s4[1]; a2 += x * s4[2]; a3 += x * s4[3];
    }
    if (OUTMODE == 0) {
        float* gp = g_Gpart + (((size_t)b * GCH + ch) * DD + d) * KK + kb;
        gp[0] = a0; gp[1] = a1; gp[2] = a2; gp[3] = a3;
    } else {
        float* xp = g_XOpart + ((size_t)b * GCH + ch) * KK * DD;
        xp[(kb+0)*DD + d] = a0; xp[(kb+1)*DD + d] = a1;
        xp[(kb+2)*DD + d] = a2; xp[(kb+3)*DD + d] = a3;
    }
}

// ---- 6. per-iteration phase C: reduce G, q = U - ((xG - nsq*s)*ninv) @ M ----
__global__ void __launch_bounds__(128) iterC_kernel(const float* __restrict__ X) {
    __shared__ float sG[DD * KK];   // 4 KB
    __shared__ float sM[KK * KK];
    int b = blockIdx.y, tid = threadIdx.x;

    for (int e = tid; e < DD * KK; e += 128) {
        float s = 0.f;
#pragma unroll
        for (int ch = 0; ch < GCH; ch++)
            s += g_Gpart[((size_t)b * GCH + ch) * DD * KK + e];
        sG[e] = s;
    }
    for (int e = tid; e < KK * KK; e += 128) sM[e] = g_M[e];
    __syncthreads();

    size_t gr = (size_t)b * NN + blockIdx.x * 128 + tid;
    const float4* xv = reinterpret_cast<const float4*>(X + gr * DD);
    float x[DD];
#pragma unroll
    for (int p = 0; p < 16; p++) {
        float4 v = xv[p];
        x[4*p] = v.x; x[4*p+1] = v.y; x[4*p+2] = v.z; x[4*p+3] = v.w;
    }
    const float* sr = g_s + gr * KK;
    float nsq = g_normsq[gr], ninv = g_norminv[gr];

    float out0[KK];
#pragma unroll
    for (int kb = 0; kb < KK; kb += 4) {
        float ax = 0, ay = 0, az = 0, aw = 0;
#pragma unroll 8
        for (int d = 0; d < DD; d++) {
            float4 g = *reinterpret_cast<const float4*>(&sG[d * KK + kb]);
            ax += x[d] * g.x; ay += x[d] * g.y;
            az += x[d] * g.z; aw += x[d] * g.w;
        }
        out0[kb+0] = (ax - nsq * sr[kb+0]) * ninv;
        out0[kb+1] = (ay - nsq * sr[kb+1]) * ninv;
        out0[kb+2] = (az - nsq * sr[kb+2]) * ninv;
        out0[kb+3] = (aw - nsq * sr[kb+3]) * ninv;
    }

    const float* Ur = g_U + gr * KK;
    float* qr = g_q + gr * KK;
#pragma unroll
    for (int k2 = 0; k2 < KK; k2++) {
        float o = 0.f;
#pragma unroll
        for (int k = 0; k < KK; k++) o += out0[k] * sM[k * KK + k2];
        qr[k2] = Ur[k2] - o;
    }
}

// ---- 9. finalize: reduce X_out partials, A_out = L^T t ----
__global__ void __launch_bounds__(512) final_kernel(float* __restrict__ out) {
    __shared__ float sA[KK * KK];
    int b = blockIdx.x, tid = threadIdx.x;

    for (int e = tid; e < KK * DD; e += 512) {
        float s = 0.f;
#pragma unroll
        for (int ch = 0; ch < GCH; ch++)
            s += g_XOpart[((size_t)b * GCH + ch) * KK * DD + e];
        out[(size_t)b * KK * DD + e] = s;
    }

    int pair = tid & 255;
    int half = tid >> 8;
    int k1 = pair >> 4, k2 = pair & 15;
    const float* L = g_s + ((size_t)b * NN + half * 1024) * KK;
    const float* t = g_t + ((size_t)b * NN + half * 1024) * KK;
    float s = 0.f;
#pragma unroll 8
    for (int i = 0; i < 1024; i++)
        s += L[i * KK + k1] * t[i * KK + k2];
    if (half == 1) sA[pair] = s;
    __syncthreads();
    if (half == 0)
        out[(size_t)BB * KK * DD + b * 256 + pair] = s + sA[pair];
}

extern "C" void kernel_launch(void* const* d_in, const int* in_sizes, int n_in,
                              void* d_out, int out_size) {
    const float* X  = (const float*)d_in[0];
    const float* A  = (const float*)d_in[1];
    const float* wf = (const float*)d_in[2];
    const float* wc = (const float*)d_in[3];
    float* out = (float*)d_out;

    prep_kernel<<<BB*NN/128, 128>>>(X);
    colsumM_kernel<<<BB + 1, 256>>>(X, wf, wc);
    norm_kernel<<<BB*NN/128, 128>>>(X);
    bigpass_kernel<0><<<dim3(NN/128, BB), 128>>>(A);
    for (int it = 0; it < ITERS; it++) {
        iterA_kernel<0><<<dim3(GCH, BB), 256>>>(X);
        iterC_kernel<<<dim3(NN/128, BB), 128>>>(X);
    }
    iterA_kernel<1><<<dim3(GCH, BB), 256>>>(X);   // L = softmax(q), X_out partials
    bigpass_kernel<1><<<dim3(NN/128, BB), 128>>>(A);  // t = A @ L
    final_kernel<<<BB, 512>>>(out);
}

// round 2
// speedup vs baseline: 3.3166x; 3.3166x over previous
#include <cuda_runtime.h>
#include <cstdint>
#include <math.h>

// StructPool: B=8, N=2048, D=64, K=16, 5 mean-field iterations.
// Restructured math (identical up to f32 rounding):
//   Xp = pool(X);  Uraw = A @ Xp  (pass 1 over A, j-split partials)
//   U = tanh(Uraw / rowsum);  norm_i = x_i.colsum - ||x_i||^2
//   iter: s=softmax(q); G=X^T s; q = U - ((xG - nsq*s)*ninv) @ M
//   L = softmax(q);  t = A @ L  (pass 2);  X_out = L^T X;  A_out = L^T t

#define BB 8
#define NN 2048
#define DD 64
#define KK 16
#define ITERS 5
#define GCH 32          // 64-row chunks for G / XO partials
#define JC 8            // j-chunks for the A passes
#define JCH 256         // rows of A per j-chunk

// ---- scratch (device globals) ----
__device__ float g_Xp[BB*NN*KK];
__device__ float g_normsq[BB*NN];
__device__ float g_norminv[BB*NN];
__device__ float g_cspart[BB*16*DD];
__device__ float g_U[BB*NN*KK];
__device__ float g_s[BB*NN*KK];      // s during iters, L at the end
__device__ float g_t[BB*NN*KK];
__device__ float g_P[(size_t)JC*BB*NN*KK];   // A-pass partials (8 MB)
__device__ float g_Gpart[BB*GCH*DD*KK];
__device__ float g_XOpart[BB*GCH*KK*DD];

// ---- packed f32x2 helpers ----
__device__ __forceinline__ unsigned long long pack2(float a) {
    unsigned long long r;
    asm("mov.b64 %0, {%1, %1};" : "=l"(r) : "f"(a));
    return r;
}
__device__ __forceinline__ unsigned long long fma2(unsigned long long a,
                                                   unsigned long long b,
                                                   unsigned long long c) {
    unsigned long long d;
    asm("fma.rn.f32x2 %0, %1, %2, %3;" : "=l"(d) : "l"(a), "l"(b), "l"(c));
    return d;
}

// ---- 1. per-row: Xp (pool) + ||x||^2 ----
__global__ void prep_kernel(const float* __restrict__ X) {
    int row = blockIdx.x * blockDim.x + threadIdx.x;
    const float4* xr = reinterpret_cast<const float4*>(X + (size_t)row * DD);
    float ns = 0.f;
    float* xp = g_Xp + (size_t)row * KK;
#pragma unroll
    for (int p = 0; p < 16; p++) {
        float4 v = xr[p];
        xp[p] = (v.x + v.y + v.z + v.w) * 0.25f;
        ns += v.x*v.x + v.y*v.y + v.z*v.z + v.w*v.w;
    }
    g_normsq[row] = ns;
}

// ---- 2. partial column sums of X per batch ----
__global__ void __launch_bounds__(256) colsum_part_kernel(const float* __restrict__ X) {
    __shared__ float sm[256];
    int ch = blockIdx.x, b = blockIdx.y;            // 16 chunks of 128 rows
    int d = threadIdx.x & 63, r4 = threadIdx.x >> 6;
    const float* base = X + ((size_t)b * NN + ch * 128 + r4) * DD + d;
    float s = 0.f;
#pragma unroll 8
    for (int i = 0; i < 32; i++) s += base[(size_t)i * 4 * DD];
    sm[threadIdx.x] = s;
    __syncthreads();
    if (threadIdx.x < 64)
        g_cspart[(b * 16 + ch) * DD + threadIdx.x] =
            sm[threadIdx.x] + sm[threadIdx.x + 64] + sm[threadIdx.x + 128] + sm[threadIdx.x + 192];
}

// ---- 3. norm_i = x_i.colsum - ||x_i||^2 (reciprocal) ----
__global__ void __launch_bounds__(128) norm_kernel(const float* __restrict__ X) {
    __shared__ float cs[DD];
    int b = blockIdx.x / 16;
    if (threadIdx.x < DD) {
        float s = 0.f;
#pragma unroll
        for (int ch = 0; ch < 16; ch++) s += g_cspart[(b * 16 + ch) * DD + threadIdx.x];
        cs[threadIdx.x] = s;
    }
    __syncthreads();
    int row = blockIdx.x * 128 + threadIdx.x;
    const float* xr = X + (size_t)row * DD;
    float dot = 0.f;
#pragma unroll
    for (int d = 0; d < DD; d++) dot += xr[d] * cs[d];
    g_norminv[row] = 1.0f / (dot - g_normsq[row]);
}

// ---- 4/8. A pass, j-split: P[jc][row][k] = sum_{j in chunk} A[j][i] * V[j][k] ----
template <int MODE>
__global__ void __launch_bounds__(128) bigpass2_kernel(const float* __restrict__ A) {
    __shared__ float sV[JCH * KK];                  // 16 KB
    int b = blockIdx.y, jc = blockIdx.z;
    int i = blockIdx.x * 128 + threadIdx.x;
    int j0 = jc * JCH;
    const float* V = (MODE == 0) ? g_Xp : g_s;
    const float* Ab = A + (size_t)b * NN * NN;

    const float4* src = reinterpret_cast<const float4*>(V + ((size_t)b * NN + j0) * KK);
    float4* dst = reinterpret_cast<float4*>(sV);
#pragma unroll
    for (int e = threadIdx.x; e < JCH * KK / 4; e += 128) dst[e] = src[e];
    __syncthreads();

    unsigned long long acc[8];
#pragma unroll
    for (int p = 0; p < 8; p++) acc[p] = 0ull;

#pragma unroll 8
    for (int j = 0; j < JCH; j++) {
        float a = Ab[(size_t)(j0 + j) * NN + i];
        unsigned long long aa = pack2(a);
        const ulonglong2* vp = reinterpret_cast<const ulonglong2*>(sV + j * KK);
        ulonglong2 v0 = vp[0], v1 = vp[1], v2 = vp[2], v3 = vp[3];
        acc[0] = fma2(aa, v0.x, acc[0]); acc[1] = fma2(aa, v0.y, acc[1]);
        acc[2] = fma2(aa, v1.x, acc[2]); acc[3] = fma2(aa, v1.y, acc[3]);
        acc[4] = fma2(aa, v2.x, acc[4]); acc[5] = fma2(aa, v2.y, acc[5]);
        acc[6] = fma2(aa, v3.x, acc[6]); acc[7] = fma2(aa, v3.y, acc[7]);
    }

    float* P = g_P + ((size_t)jc * BB * NN + (size_t)b * NN + i) * KK;
    ulonglong2* Pv = reinterpret_cast<ulonglong2*>(P);
    Pv[0] = make_ulonglong2(acc[0], acc[1]);
    Pv[1] = make_ulonglong2(acc[2], acc[3]);
    Pv[2] = make_ulonglong2(acc[4], acc[5]);
    Pv[3] = make_ulonglong2(acc[6], acc[7]);
}

// ---- 5. postU: reduce P -> Uraw, U=tanh, s0=softmax(U), Gpart0 ----
__global__ void __launch_bounds__(256) postU_kernel(const float* __restrict__ X) {
    __shared__ float ss[64 * KK];
    int b = blockIdx.y, ch = blockIdx.x, tid = threadIdx.x;
    int lr = tid >> 2, kq = tid & 3;
    size_t row = (size_t)b * NN + ch * 64 + lr;

    float4 u4 = make_float4(0.f, 0.f, 0.f, 0.f);
#pragma unroll
    for (int jc = 0; jc < JC; jc++) {
        float4 p = *reinterpret_cast<const float4*>(
            g_P + ((size_t)jc * BB * NN + row) * KK + kq * 4);
        u4.x += p.x; u4.y += p.y; u4.z += p.z; u4.w += p.w;
    }
    float lsum = u4.x + u4.y + u4.z + u4.w;
    lsum += __shfl_xor_sync(0xffffffffu, lsum, 1);
    lsum += __shfl_xor_sync(0xffffffffu, lsum, 2);
    float inv = 1.0f / lsum;
    float u0 = tanhf(u4.x * inv), u1 = tanhf(u4.y * inv);
    float u2 = tanhf(u4.z * inv), u3 = tanhf(u4.w * inv);
    *reinterpret_cast<float4*>(g_U + row * KK + kq * 4) = make_float4(u0, u1, u2, u3);

    float m = fmaxf(fmaxf(u0, u1), fmaxf(u2, u3));
    m = fmaxf(m, __shfl_xor_sync(0xffffffffu, m, 1));
    m = fmaxf(m, __shfl_xor_sync(0xffffffffu, m, 2));
    float e0 = expf(u0 - m), e1 = expf(u1 - m), e2 = expf(u2 - m), e3 = expf(u3 - m);
    float es = e0 + e1 + e2 + e3;
    es += __shfl_xor_sync(0xffffffffu, es, 1);
    es += __shfl_xor_sync(0xffffffffu, es, 2);
    float si = 1.0f / es;
    float4 sv = make_float4(e0 * si, e1 * si, e2 * si, e3 * si);
    *reinterpret_cast<float4*>(g_s + row * KK + kq * 4) = sv;
    *reinterpret_cast<float4*>(&ss[lr * KK + kq * 4]) = sv;
    __syncthreads();

    int d = tid & 63, kb = (tid >> 6) * 4;
    float a0 = 0, a1 = 0, a2 = 0, a3 = 0;
    const float* Xb = X + ((size_t)b * NN + ch * 64) * DD + d;
#pragma unroll 4
    for (int i2 = 0; i2 < 64; i2++) {
        float x = Xb[(size_t)i2 * DD];
        const float* s4 = &ss[i2 * KK + kb];
        a0 += x * s4[0]; a1 += x * s4[1]; a2 += x * s4[2]; a3 += x * s4[3];
    }
    float* gp = g_Gpart + (((size_t)b * GCH + ch) * DD + d) * KK + kb;
    gp[0] = a0; gp[1] = a1; gp[2] = a2; gp[3] = a3;
}

// ---- 6/7. fused iteration: G-reduce, q=U-out@M, s'=softmax(q), next partials ----
// LAST=0: write Gpart(next).  LAST=1: write XOpart (s' = L, stored to g_s).
template <int LAST>
__global__ void __launch_bounds__(256) iter_kernel(const float* __restrict__ X,
                                                   const float* __restrict__ wf,
                                                   const float* __restrict__ wc) {
    __shared__ float sG[DD * KK];
    __shared__ float sM[KK * KK];
    __shared__ float ss[64 * KK];
    int b = blockIdx.y, ch = blockIdx.x, tid = threadIdx.x;

    {   // reduce G partials (1024 el, 4 consecutive per thread)
        float4 acc = make_float4(0.f, 0.f, 0.f, 0.f);
#pragma unroll
        for (int c2 = 0; c2 < GCH; c2++) {
            float4 p = *reinterpret_cast<const float4*>(
                g_Gpart + ((size_t)b * GCH + c2) * DD * KK + tid * 4);
            acc.x += p.x; acc.y += p.y; acc.z += p.z; acc.w += p.w;
        }
        *reinterpret_cast<float4*>(&sG[tid * 4]) = acc;
        // M = wf @ wc
        int k1 = tid >> 4, k2 = tid & 15;
        float mm = 0.f;
#pragma unroll
        for (int k = 0; k < KK; k++) mm += wf[k1 * KK + k] * wc[k * KK + k2];
        sM[tid] = mm;
    }
    __syncthreads();

    int lr = tid >> 2, dq = tid & 3;
    size_t row = (size_t)b * NN + ch * 64 + lr;

    // xg = x . G over this thread's 16-d slice, then 4-lane reduce
    float x[16];
    const float4* xv = reinterpret_cast<const float4*>(X + row * DD + dq * 16);
#pragma unroll
    for (int p = 0; p < 4; p++) {
        float4 v = xv[p];
        x[4*p] = v.x; x[4*p+1] = v.y; x[4*p+2] = v.z; x[4*p+3] = v.w;
    }
    float xg[KK];
#pragma unroll
    for (int k = 0; k < KK; k++) xg[k] = 0.f;
#pragma unroll
    for (int dd = 0; dd < 16; dd++) {
        float xd = x[dd];
        const float* g = &sG[(dq * 16 + dd) * KK];
#pragma unroll
        for (int k = 0; k < KK; k++) xg[k] += xd * g[k];
    }
#pragma unroll
    for (int k = 0; k < KK; k++) {
        xg[k] += __shfl_xor_sync(0xffffffffu, xg[k], 1);
        xg[k] += __shfl_xor_sync(0xffffffffu, xg[k], 2);
    }

    float sprev[KK];
#pragma unroll
    for (int p = 0; p < 4; p++) {
        float4 v = *reinterpret_cast<const float4*>(g_s + row * KK + p * 4);
        sprev[4*p] = v.x; sprev[4*p+1] = v.y; sprev[4*p+2] = v.z; sprev[4*p+3] = v.w;
    }
    float nsq = g_normsq[row], ninv = g_norminv[row];
    float out0[KK];
#pragma unroll
    for (int k = 0; k < KK; k++) out0[k] = (xg[k] - nsq * sprev[k]) * ninv;

    // q for this thread's k-quad
    float4 Uq = *reinterpret_cast<const float4*>(g_U + row * KK + dq * 4);
    float q[4] = {Uq.x, Uq.y, Uq.z, Uq.w};
#pragma unroll
    for (int k = 0; k < KK; k++) {
        const float* Mr = &sM[k * KK + dq * 4];
        q[0] -= out0[k] * Mr[0]; q[1] -= out0[k] * Mr[1];
        q[2] -= out0[k] * Mr[2]; q[3] -= out0[k] * Mr[3];
    }
    float m = fmaxf(fmaxf(q[0], q[1]), fmaxf(q[2], q[3]));
    m = fmaxf(m, __shfl_xor_sync(0xffffffffu, m, 1));
    m = fmaxf(m, __shfl_xor_sync(0xffffffffu, m, 2));
    float e0 = expf(q[0]-m), e1 = expf(q[1]-m), e2 = expf(q[2]-m), e3 = expf(q[3]-m);
    float es = e0 + e1 + e2 + e3;
    es += __shfl_xor_sync(0xffffffffu, es, 1);
    es += __shfl_xor_sync(0xffffffffu, es, 2);
    float si = 1.0f / es;
    float4 sv = make_float4(e0*si, e1*si, e2*si, e3*si);
    *reinterpret_cast<float4*>(g_s + row * KK + dq * 4) = sv;
    *reinterpret_cast<float4*>(&ss[lr * KK + dq * 4]) = sv;
    __syncthreads();

    int d = tid & 63, kb = (tid >> 6) * 4;
    float a0 = 0, a1 = 0, a2 = 0, a3 = 0;
    const float* Xb = X + ((size_t)b * NN + ch * 64) * DD + d;
#pragma unroll 4
    for (int i2 = 0; i2 < 64; i2++) {
        float xx = Xb[(size_t)i2 * DD];
        const float* s4 = &ss[i2 * KK + kb];
        a0 += xx * s4[0]; a1 += xx * s4[1]; a2 += xx * s4[2]; a3 += xx * s4[3];
    }
    if (LAST == 0) {
        float* gp = g_Gpart + (((size_t)b * GCH + ch) * DD + d) * KK + kb;
        gp[0] = a0; gp[1] = a1; gp[2] = a2; gp[3] = a3;
    } else {
        float* xp = g_XOpart + ((size_t)b * GCH + ch) * KK * DD;
        xp[(kb+0)*DD + d] = a0; xp[(kb+1)*DD + d] = a1;
        xp[(kb+2)*DD + d] = a2; xp[(kb+3)*DD + d] = a3;
    }
}

// ---- 9. reduce t partials ----
__global__ void __launch_bounds__(256) reduceT_kernel() {
    size_t row = (size_t)blockIdx.x * 256 + threadIdx.x;
    float4 t0 = make_float4(0,0,0,0), t1 = t0, t2 = t0, t3 = t0;
#pragma unroll
    for (int jc = 0; jc < JC; jc++) {
        const float4* p = reinterpret_cast<const float4*>(
            g_P + ((size_t)jc * BB * NN + row) * KK);
        float4 a = p[0], bq = p[1], c = p[2], dd = p[3];
        t0.x += a.x; t0.y += a.y; t0.z += a.z; t0.w += a.w;
        t1.x += bq.x; t1.y += bq.y; t1.z += bq.z; t1.w += bq.w;
        t2.x += c.x; t2.y += c.y; t2.z += c.z; t2.w += c.w;
        t3.x += dd.x; t3.y += dd.y; t3.z += dd.z; t3.w += dd.w;
    }
    float4* t = reinterpret_cast<float4*>(g_t + row * KK);
    t[0] = t0; t[1] = t1; t[2] = t2; t[3] = t3;
}

// ---- 10. finalize: X_out partial reduce + A_out = L^T t ----
__global__ void __launch_bounds__(512) final_kernel(float* __restrict__ out) {
    __shared__ float sA[KK * KK];
    int b = blockIdx.x, tid = threadIdx.x;

    for (int e = tid; e < KK * DD; e += 512) {
        float s = 0.f;
#pragma unroll
        for (int ch = 0; ch < GCH; ch++)
            s += g_XOpart[((size_t)b * GCH + ch) * KK * DD + e];
        out[(size_t)b * KK * DD + e] = s;
    }

    int pair = tid & 255;
    int half = tid >> 8;
    int k1 = pair >> 4, k2 = pair & 15;
    const float* L = g_s + ((size_t)b * NN + half * 1024) * KK;
    const float* t = g_t + ((size_t)b * NN + half * 1024) * KK;
    float s = 0.f;
#pragma unroll 8
    for (int i = 0; i < 1024; i++)
        s += L[i * KK + k1] * t[i * KK + k2];
    if (half == 1) sA[pair] = s;
    __syncthreads();
    if (half == 0)
        out[(size_t)BB * KK * DD + b * 256 + pair] = s + sA[pair];
}

extern "C" void kernel_launch(void* const* d_in, const int* in_sizes, int n_in,
                              void* d_out, int out_size) {
    const float* X  = (const float*)d_in[0];
    const float* A  = (const float*)d_in[1];
    const float* wf = (const float*)d_in[2];
    const float* wc = (const float*)d_in[3];
    float* out = (float*)d_out;

    prep_kernel<<<BB*NN/128, 128>>>(X);
    colsum_part_kernel<<<dim3(16, BB), 256>>>(X);
    norm_kernel<<<BB*NN/128, 128>>>(X);
    bigpass2_kernel<0><<<dim3(NN/128, BB, JC), 128>>>(A);
    postU_kernel<<<dim3(GCH, BB), 256>>>(X);
    for (int it = 0; it < ITERS - 1; it++)
        iter_kernel<0><<<dim3(GCH, BB), 256>>>(X, wf, wc);
    iter_kernel<1><<<dim3(GCH, BB), 256>>>(X, wf, wc);   // L, X_out partials
    bigpass2_kernel<1><<<dim3(NN/128, BB, JC), 128>>>(A);
    reduceT_kernel<<<BB*NN/256, 256>>>();
    final_kernel<<<BB, 512>>>(out);
}

// round 3
// speedup vs baseline: 3.9246x; 1.1833x over previous
#include <cuda_runtime.h>
#include <cstdint>
#include <math.h>

// StructPool: B=8, N=2048, D=64, K=16, 5 mean-field iterations.

#define BB 8
#define NN 2048
#define DD 64
#define KK 16
#define ITERS 5
#define GCH 16          // 128-row chunks for G / XO partials
#define JC 16           // j-chunks for the A passes
#define JCH 128         // rows of A per j-chunk
#define RPB 128         // rows per iteration block

// ---- scratch ----
__device__ float g_Xp[BB*NN*KK];
__device__ float g_normsq[BB*NN];
__device__ float g_norminv[BB*NN];
__device__ float g_cspart[BB*16*DD];
__device__ float g_U[BB*NN*KK];
__device__ float g_s[BB*NN*KK];
__device__ float g_t[BB*NN*KK];
__device__ float g_P[(size_t)JC*BB*NN*KK];     // 16 MB
__device__ float g_Gpart[BB*GCH*DD*KK];
__device__ float g_XOpart[BB*GCH*KK*DD];

// ---- packed f32x2 helpers ----
__device__ __forceinline__ unsigned long long pack2(float a) {
    unsigned long long r;
    asm("mov.b64 %0, {%1, %1};" : "=l"(r) : "f"(a));
    return r;
}
__device__ __forceinline__ unsigned long long fma2(unsigned long long a,
                                                   unsigned long long b,
                                                   unsigned long long c) {
    unsigned long long d;
    asm("fma.rn.f32x2 %0, %1, %2, %3;" : "=l"(d) : "l"(a), "l"(b), "l"(c));
    return d;
}

// ---- 1. merged colsum-partials + row prep (Xp, ||x||^2) ----
__global__ void __launch_bounds__(256) prepcs_kernel(const float* __restrict__ X) {
    __shared__ float sm[256];
    int ch = blockIdx.x, b = blockIdx.y;
    int d = threadIdx.x & 63, r4 = threadIdx.x >> 6;
    const float* base = X + ((size_t)b * NN + ch * 128 + r4) * DD + d;
    float s = 0.f;
#pragma unroll 8
    for (int i = 0; i < 32; i++) s += base[(size_t)i * 4 * DD];
    sm[threadIdx.x] = s;
    __syncthreads();
    if (threadIdx.x < 64)
        g_cspart[(b * 16 + ch) * DD + threadIdx.x] =
            sm[threadIdx.x] + sm[threadIdx.x + 64] + sm[threadIdx.x + 128] + sm[threadIdx.x + 192];

    if (threadIdx.x < 128) {
        size_t row = (size_t)b * NN + ch * 128 + threadIdx.x;
        const float4* xr = reinterpret_cast<const float4*>(X + row * DD);
        float ns = 0.f;
        float* xp = g_Xp + row * KK;
#pragma unroll
        for (int p = 0; p < 16; p++) {
            float4 v = xr[p];
            xp[p] = (v.x + v.y + v.z + v.w) * 0.25f;
            ns += v.x*v.x + v.y*v.y + v.z*v.z + v.w*v.w;
        }
        g_normsq[row] = ns;
    }
}

// ---- 2. norm_i = 1 / (x_i.colsum - ||x_i||^2) ----
__global__ void __launch_bounds__(128) norm_kernel(const float* __restrict__ X) {
    __shared__ float cs[DD];
    int b = blockIdx.x / 16;
    if (threadIdx.x < DD) {
        float s = 0.f;
#pragma unroll
        for (int ch = 0; ch < 16; ch++) s += g_cspart[(b * 16 + ch) * DD + threadIdx.x];
        cs[threadIdx.x] = s;
    }
    __syncthreads();
    int row = blockIdx.x * 128 + threadIdx.x;
    const float* xr = X + (size_t)row * DD;
    float dot = 0.f;
#pragma unroll
    for (int d = 0; d < DD; d++) dot += xr[d] * cs[d];
    g_norminv[row] = 1.0f / (dot - g_normsq[row]);
}

// ---- 3/8. A pass: 4 output columns per thread, float4 streaming A loads ----
template <int MODE>
__global__ void __launch_bounds__(128) bigpass3_kernel(const float* __restrict__ A) {
    __shared__ float sV[JCH * KK];                  // 8 KB
    int b = blockIdx.y, jc = blockIdx.z;
    int i0 = blockIdx.x * 512 + threadIdx.x * 4;    // 4 consecutive output cols
    int j0 = jc * JCH;
    const float* V = (MODE == 0) ? g_Xp : g_s;
    const float* Ab = A + (size_t)b * NN * NN;

    {   // stage V chunk
        const float4* src = reinterpret_cast<const float4*>(V + ((size_t)b * NN + j0) * KK);
        float4* dst = reinterpret_cast<float4*>(sV);
#pragma unroll
        for (int e = threadIdx.x; e < JCH * KK / 4; e += 128) dst[e] = src[e];
    }
    __syncthreads();

    unsigned long long acc[4][8];
#pragma unroll
    for (int ii = 0; ii < 4; ii++)
#pragma unroll
        for (int p = 0; p < 8; p++) acc[ii][p] = 0ull;

#pragma unroll 4
    for (int j = 0; j < JCH; j++) {
        float4 a = __ldcs(reinterpret_cast<const float4*>(Ab + (size_t)(j0 + j) * NN + i0));
        unsigned long long aa0 = pack2(a.x), aa1 = pack2(a.y);
        unsigned long long aa2 = pack2(a.z), aa3 = pack2(a.w);
        const ulonglong2* vp = reinterpret_cast<const ulonglong2*>(sV + j * KK);
        ulonglong2 v0 = vp[0], v1 = vp[1], v2 = vp[2], v3 = vp[3];
        acc[0][0] = fma2(aa0, v0.x, acc[0][0]); acc[0][1] = fma2(aa0, v0.y, acc[0][1]);
        acc[0][2] = fma2(aa0, v1.x, acc[0][2]); acc[0][3] = fma2(aa0, v1.y, acc[0][3]);
        acc[0][4] = fma2(aa0, v2.x, acc[0][4]); acc[0][5] = fma2(aa0, v2.y, acc[0][5]);
        acc[0][6] = fma2(aa0, v3.x, acc[0][6]); acc[0][7] = fma2(aa0, v3.y, acc[0][7]);
        acc[1][0] = fma2(aa1, v0.x, acc[1][0]); acc[1][1] = fma2(aa1, v0.y, acc[1][1]);
        acc[1][2] = fma2(aa1, v1.x, acc[1][2]); acc[1][3] = fma2(aa1, v1.y, acc[1][3]);
        acc[1][4] = fma2(aa1, v2.x, acc[1][4]); acc[1][5] = fma2(aa1, v2.y, acc[1][5]);
        acc[1][6] = fma2(aa1, v3.x, acc[1][6]); acc[1][7] = fma2(aa1, v3.y, acc[1][7]);
        acc[2][0] = fma2(aa2, v0.x, acc[2][0]); acc[2][1] = fma2(aa2, v0.y, acc[2][1]);
        acc[2][2] = fma2(aa2, v1.x, acc[2][2]); acc[2][3] = fma2(aa2, v1.y, acc[2][3]);
        acc[2][4] = fma2(aa2, v2.x, acc[2][4]); acc[2][5] = fma2(aa2, v2.y, acc[2][5]);
        acc[2][6] = fma2(aa2, v3.x, acc[2][6]); acc[2][7] = fma2(aa2, v3.y, acc[2][7]);
        acc[3][0] = fma2(aa3, v0.x, acc[3][0]); acc[3][1] = fma2(aa3, v0.y, acc[3][1]);
        acc[3][2] = fma2(aa3, v1.x, acc[3][2]); acc[3][3] = fma2(aa3, v1.y, acc[3][3]);
        acc[3][4] = fma2(aa3, v2.x, acc[3][4]); acc[3][5] = fma2(aa3, v2.y, acc[3][5]);
        acc[3][6] = fma2(aa3, v3.x, acc[3][6]); acc[3][7] = fma2(aa3, v3.y, acc[3][7]);
    }

#pragma unroll
    for (int ii = 0; ii < 4; ii++) {
        float* P = g_P + ((size_t)jc * BB * NN + (size_t)b * NN + i0 + ii) * KK;
        ulonglong2* Pv = reinterpret_cast<ulonglong2*>(P);
        Pv[0] = make_ulonglong2(acc[ii][0], acc[ii][1]);
        Pv[1] = make_ulonglong2(acc[ii][2], acc[ii][3]);
        Pv[2] = make_ulonglong2(acc[ii][4], acc[ii][5]);
        Pv[3] = make_ulonglong2(acc[ii][6], acc[ii][7]);
    }
}

// ---- shared epilogue: softmax over a 4-lane k-quad ----
__device__ __forceinline__ float4 quad_softmax(float q0, float q1, float q2, float q3) {
    float m = fmaxf(fmaxf(q0, q1), fmaxf(q2, q3));
    m = fmaxf(m, __shfl_xor_sync(0xffffffffu, m, 1));
    m = fmaxf(m, __shfl_xor_sync(0xffffffffu, m, 2));
    float e0 = expf(q0-m), e1 = expf(q1-m), e2 = expf(q2-m), e3 = expf(q3-m);
    float es = e0 + e1 + e2 + e3;
    es += __shfl_xor_sync(0xffffffffu, es, 1);
    es += __shfl_xor_sync(0xffffffffu, es, 2);
    float si = 1.0f / es;
    return make_float4(e0*si, e1*si, e2*si, e3*si);
}

// ---- Gpart / XOpart producer phase (128-row chunk, 512 threads) ----
template <int LAST>
__device__ __forceinline__ void produce_parts(const float* __restrict__ X,
                                              const float* ss, int b, int ch, int tid) {
    int d = tid & 63, kb = (tid >> 6) * 2;      // 8 groups x 2 k
    float a0 = 0.f, a1 = 0.f;
    const float* Xb = X + ((size_t)b * NN + ch * RPB) * DD + d;
#pragma unroll 4
    for (int i2 = 0; i2 < RPB; i2++) {
        float x = Xb[(size_t)i2 * DD];
        const float* s2 = &ss[i2 * KK + kb];
        a0 += x * s2[0]; a1 += x * s2[1];
    }
    if (LAST == 0) {
        float* gp = g_Gpart + (((size_t)b * GCH + ch) * DD + d) * KK + kb;
        gp[0] = a0; gp[1] = a1;
    } else {
        float* xp = g_XOpart + ((size_t)b * GCH + ch) * KK * DD;
        xp[(kb+0)*DD + d] = a0; xp[(kb+1)*DD + d] = a1;
    }
}

// ---- 4. postU: reduce P -> U=tanh, s0=softmax(U), Gpart0 ----
__global__ void __launch_bounds__(512) postU_kernel(const float* __restrict__ X) {
    __shared__ float ss[RPB * KK];
    int b = blockIdx.y, ch = blockIdx.x, tid = threadIdx.x;
    int lr = tid >> 2, kq = tid & 3;
    size_t row = (size_t)b * NN + ch * RPB + lr;

    float4 u4 = make_float4(0.f, 0.f, 0.f, 0.f);
#pragma unroll
    for (int jc = 0; jc < JC; jc++) {
        float4 p = *reinterpret_cast<const float4*>(
            g_P + ((size_t)jc * BB * NN + row) * KK + kq * 4);
        u4.x += p.x; u4.y += p.y; u4.z += p.z; u4.w += p.w;
    }
    float lsum = u4.x + u4.y + u4.z + u4.w;
    lsum += __shfl_xor_sync(0xffffffffu, lsum, 1);
    lsum += __shfl_xor_sync(0xffffffffu, lsum, 2);
    float inv = 1.0f / lsum;
    float u0 = tanhf(u4.x * inv), u1 = tanhf(u4.y * inv);
    float u2 = tanhf(u4.z * inv), u3 = tanhf(u4.w * inv);
    *reinterpret_cast<float4*>(g_U + row * KK + kq * 4) = make_float4(u0, u1, u2, u3);

    float4 sv = quad_softmax(u0, u1, u2, u3);
    *reinterpret_cast<float4*>(g_s + row * KK + kq * 4) = sv;
    *reinterpret_cast<float4*>(&ss[lr * KK + kq * 4]) = sv;
    __syncthreads();

    produce_parts<0>(X, ss, b, ch, tid);
}

// ---- 5. fused mean-field iteration ----
template <int LAST>
__global__ void __launch_bounds__(512) iter_kernel(const float* __restrict__ X,
                                                   const float* __restrict__ wf,
                                                   const float* __restrict__ wc) {
    __shared__ float sG[DD * KK];
    __shared__ float sM[KK * KK];
    __shared__ float ss[RPB * KK];
    int b = blockIdx.y, ch = blockIdx.x, tid = threadIdx.x;

    if (tid < 256) {            // G reduce (1024 floats)
        float4 acc = make_float4(0.f, 0.f, 0.f, 0.f);
#pragma unroll
        for (int c2 = 0; c2 < GCH; c2++) {
            float4 p = *reinterpret_cast<const float4*>(
                g_Gpart + ((size_t)b * GCH + c2) * DD * KK + tid * 4);
            acc.x += p.x; acc.y += p.y; acc.z += p.z; acc.w += p.w;
        }
        *reinterpret_cast<float4*>(&sG[tid * 4]) = acc;
    } else {                    // M = wf @ wc
        int t = tid - 256;
        int k1 = t >> 4, k2 = t & 15;
        float mm = 0.f;
#pragma unroll
        for (int k = 0; k < KK; k++) mm += wf[k1 * KK + k] * wc[k * KK + k2];
        sM[t] = mm;
    }
    __syncthreads();

    int lr = tid >> 2, dq = tid & 3;
    size_t row = (size_t)b * NN + ch * RPB + lr;

    float x[16];
    const float4* xv = reinterpret_cast<const float4*>(X + row * DD + dq * 16);
#pragma unroll
    for (int p = 0; p < 4; p++) {
        float4 v = xv[p];
        x[4*p] = v.x; x[4*p+1] = v.y; x[4*p+2] = v.z; x[4*p+3] = v.w;
    }
    float xg[KK];
#pragma unroll
    for (int k = 0; k < KK; k++) xg[k] = 0.f;
#pragma unroll
    for (int dd = 0; dd < 16; dd++) {
        float xd = x[dd];
        const float* g = &sG[(dq * 16 + dd) * KK];
#pragma unroll
        for (int k = 0; k < KK; k++) xg[k] += xd * g[k];
    }
#pragma unroll
    for (int k = 0; k < KK; k++) {
        xg[k] += __shfl_xor_sync(0xffffffffu, xg[k], 1);
        xg[k] += __shfl_xor_sync(0xffffffffu, xg[k], 2);
    }

    float sprev[KK];
#pragma unroll
    for (int p = 0; p < 4; p++) {
        float4 v = *reinterpret_cast<const float4*>(g_s + row * KK + p * 4);
        sprev[4*p] = v.x; sprev[4*p+1] = v.y; sprev[4*p+2] = v.z; sprev[4*p+3] = v.w;
    }
    float nsq = g_normsq[row], ninv = g_norminv[row];
    float out0[KK];
#pragma unroll
    for (int k = 0; k < KK; k++) out0[k] = (xg[k] - nsq * sprev[k]) * ninv;

    float4 Uq = *reinterpret_cast<const float4*>(g_U + row * KK + dq * 4);
    float q0 = Uq.x, q1 = Uq.y, q2 = Uq.z, q3 = Uq.w;
#pragma unroll
    for (int k = 0; k < KK; k++) {
        const float* Mr = &sM[k * KK + dq * 4];
        q0 -= out0[k] * Mr[0]; q1 -= out0[k] * Mr[1];
        q2 -= out0[k] * Mr[2]; q3 -= out0[k] * Mr[3];
    }
    float4 sv = quad_softmax(q0, q1, q2, q3);
    *reinterpret_cast<float4*>(g_s + row * KK + dq * 4) = sv;
    *reinterpret_cast<float4*>(&ss[lr * KK + dq * 4]) = sv;
    __syncthreads();

    produce_parts<LAST>(X, ss, b, ch, tid);
}

// ---- 6. reduce t partials ----
__global__ void __launch_bounds__(256) reduceT_kernel() {
    size_t row = (size_t)blockIdx.x * 256 + threadIdx.x;
    float4 t0 = make_float4(0,0,0,0), t1 = t0, t2 = t0, t3 = t0;
#pragma unroll
    for (int jc = 0; jc < JC; jc++) {
        const float4* p = reinterpret_cast<const float4*>(
            g_P + ((size_t)jc * BB * NN + row) * KK);
        float4 a = p[0], bq = p[1], c = p[2], dd = p[3];
        t0.x += a.x; t0.y += a.y; t0.z += a.z; t0.w += a.w;
        t1.x += bq.x; t1.y += bq.y; t1.z += bq.z; t1.w += bq.w;
        t2.x += c.x; t2.y += c.y; t2.z += c.z; t2.w += c.w;
        t3.x += dd.x; t3.y += dd.y; t3.z += dd.z; t3.w += dd.w;
    }
    float4* t = reinterpret_cast<float4*>(g_t + row * KK);
    t[0] = t0; t[1] = t1; t[2] = t2; t[3] = t3;
}

// ---- 7. finalize ----
__global__ void __launch_bounds__(512) final_kernel(float* __restrict__ out) {
    __shared__ float sA[KK * KK];
    int b = blockIdx.x, tid = threadIdx.x;

    for (int e = tid; e < KK * DD; e += 512) {
        float s = 0.f;
#pragma unroll
        for (int ch = 0; ch < GCH; ch++)
            s += g_XOpart[((size_t)b * GCH + ch) * KK * DD + e];
        out[(size_t)b * KK * DD + e] = s;
    }

    int pair = tid & 255;
    int half = tid >> 8;
    int k1 = pair >> 4, k2 = pair & 15;
    const float* L = g_s + ((size_t)b * NN + half * 1024) * KK;
    const float* t = g_t + ((size_t)b * NN + half * 1024) * KK;
    float s = 0.f;
#pragma unroll 8
    for (int i = 0; i < 1024; i++)
        s += L[i * KK + k1] * t[i * KK + k2];
    if (half == 1) sA[pair] = s;
    __syncthreads();
    if (half == 0)
        out[(size_t)BB * KK * DD + b * 256 + pair] = s + sA[pair];
}

extern "C" void kernel_launch(void* const* d_in, const int* in_sizes, int n_in,
                              void* d_out, int out_size) {
    const float* X  = (const float*)d_in[0];
    const float* A  = (const float*)d_in[1];
    const float* wf = (const float*)d_in[2];
    const float* wc = (const float*)d_in[3];
    float* out = (float*)d_out;

    prepcs_kernel<<<dim3(16, BB), 256>>>(X);
    norm_kernel<<<BB*NN/128, 128>>>(X);
    bigpass3_kernel<0><<<dim3(NN/512, BB, JC), 128>>>(A);
    postU_kernel<<<dim3(GCH, BB), 512>>>(X);
    for (int it = 0; it < ITERS - 1; it++)
        iter_kernel<0><<<dim3(GCH, BB), 512>>>(X, wf, wc);
    iter_kernel<1><<<dim3(GCH, BB), 512>>>(X, wf, wc);
    bigpass3_kernel<1><<<dim3(NN/512, BB, JC), 128>>>(A);
    reduceT_kernel<<<BB*NN/256, 256>>>();
    final_kernel<<<BB, 512>>>(out);
}

// round 4
// speedup vs baseline: 4.3310x; 1.1035x over previous
#include <cuda_runtime.h>
#include <cstdint>
#include <math.h>

// StructPool: B=8, N=2048, D=64, K=16, 5 mean-field iterations.

#define BB 8
#define NN 2048
#define DD 64
#define KK 16
#define ITERS 5
#define GCH 16          // 128-row chunks (= mega blocks per batch)
#define JC 16           // j-chunks for the A passes
#define JCH 128
#define RPB 128

// ---- scratch ----
__device__ float g_Xp[BB*NN*KK];
__device__ float g_cspart[BB*GCH*DD];
__device__ float g_s[BB*NN*KK];                 // L at the end
__device__ float g_t[BB*NN*KK];
__device__ float g_P[(size_t)BB*NN*JC*KK];      // [row][jc][16], 16 MB
__device__ float g_Gpart[BB*GCH*DD*KK];
__device__ float g_XOpart[BB*GCH*KK*DD];
__device__ unsigned g_bar;

// ---- packed f32x2 ----
__device__ __forceinline__ unsigned long long pack2(float a) {
    unsigned long long r;
    asm("mov.b64 %0, {%1, %1};" : "=l"(r) : "f"(a));
    return r;
}
__device__ __forceinline__ unsigned long long fma2(unsigned long long a,
                                                   unsigned long long b,
                                                   unsigned long long c) {
    unsigned long long d;
    asm("fma.rn.f32x2 %0, %1, %2, %3;" : "=l"(d) : "l"(a), "l"(b), "l"(c));
    return d;
}

// ---- 1. prep: Xp + reset grid barrier ----
__global__ void prep_kernel(const float* __restrict__ X) {
    if (blockIdx.x == 0 && threadIdx.x == 0) g_bar = 0u;
    int row = blockIdx.x * blockDim.x + threadIdx.x;
    const float4* xr = reinterpret_cast<const float4*>(X + (size_t)row * DD);
    float* xp = g_Xp + (size_t)row * KK;
#pragma unroll
    for (int p = 0; p < 16; p++) {
        float4 v = xr[p];
        xp[p] = (v.x + v.y + v.z + v.w) * 0.25f;
    }
}

// ---- 2/5. A pass: P[row][jc][16] partials ----
template <int MODE>
__global__ void __launch_bounds__(128) bigpass3_kernel(const float* __restrict__ A) {
    __shared__ float sV[JCH * KK];
    int b = blockIdx.y, jc = blockIdx.z;
    int i0 = blockIdx.x * 512 + threadIdx.x * 4;
    int j0 = jc * JCH;
    const float* V = (MODE == 0) ? g_Xp : g_s;
    const float* Ab = A + (size_t)b * NN * NN;

    {
        const float4* src = reinterpret_cast<const float4*>(V + ((size_t)b * NN + j0) * KK);
        float4* dst = reinterpret_cast<float4*>(sV);
#pragma unroll
        for (int e = threadIdx.x; e < JCH * KK / 4; e += 128) dst[e] = src[e];
    }
    __syncthreads();

    unsigned long long acc[4][8];
#pragma unroll
    for (int ii = 0; ii < 4; ii++)
#pragma unroll
        for (int p = 0; p < 8; p++) acc[ii][p] = 0ull;

#pragma unroll 4
    for (int j = 0; j < JCH; j++) {
        float4 a = __ldcs(reinterpret_cast<const float4*>(Ab + (size_t)(j0 + j) * NN + i0));
        unsigned long long aa0 = pack2(a.x), aa1 = pack2(a.y);
        unsigned long long aa2 = pack2(a.z), aa3 = pack2(a.w);
        const ulonglong2* vp = reinterpret_cast<const ulonglong2*>(sV + j * KK);
        ulonglong2 v0 = vp[0], v1 = vp[1], v2 = vp[2], v3 = vp[3];
        acc[0][0] = fma2(aa0, v0.x, acc[0][0]); acc[0][1] = fma2(aa0, v0.y, acc[0][1]);
        acc[0][2] = fma2(aa0, v1.x, acc[0][2]); acc[0][3] = fma2(aa0, v1.y, acc[0][3]);
        acc[0][4] = fma2(aa0, v2.x, acc[0][4]); acc[0][5] = fma2(aa0, v2.y, acc[0][5]);
        acc[0][6] = fma2(aa0, v3.x, acc[0][6]); acc[0][7] = fma2(aa0, v3.y, acc[0][7]);
        acc[1][0] = fma2(aa1, v0.x, acc[1][0]); acc[1][1] = fma2(aa1, v0.y, acc[1][1]);
        acc[1][2] = fma2(aa1, v1.x, acc[1][2]); acc[1][3] = fma2(aa1, v1.y, acc[1][3]);
        acc[1][4] = fma2(aa1, v2.x, acc[1][4]); acc[1][5] = fma2(aa1, v2.y, acc[1][5]);
        acc[1][6] = fma2(aa1, v3.x, acc[1][6]); acc[1][7] = fma2(aa1, v3.y, acc[1][7]);
        acc[2][0] = fma2(aa2, v0.x, acc[2][0]); acc[2][1] = fma2(aa2, v0.y, acc[2][1]);
        acc[2][2] = fma2(aa2, v1.x, acc[2][2]); acc[2][3] = fma2(aa2, v1.y, acc[2][3]);
        acc[2][4] = fma2(aa2, v2.x, acc[2][4]); acc[2][5] = fma2(aa2, v2.y, acc[2][5]);
        acc[2][6] = fma2(aa2, v3.x, acc[2][6]); acc[2][7] = fma2(aa2, v3.y, acc[2][7]);
        acc[3][0] = fma2(aa3, v0.x, acc[3][0]); acc[3][1] = fma2(aa3, v0.y, acc[3][1]);
        acc[3][2] = fma2(aa3, v1.x, acc[3][2]); acc[3][3] = fma2(aa3, v1.y, acc[3][3]);
        acc[3][4] = fma2(aa3, v2.x, acc[3][4]); acc[3][5] = fma2(aa3, v2.y, acc[3][5]);
        acc[3][6] = fma2(aa3, v3.x, acc[3][6]); acc[3][7] = fma2(aa3, v3.y, acc[3][7]);
    }

#pragma unroll
    for (int ii = 0; ii < 4; ii++) {
        float* P = g_P + (((size_t)b * NN + i0 + ii) * JC + jc) * KK;
        ulonglong2* Pv = reinterpret_cast<ulonglong2*>(P);
        Pv[0] = make_ulonglong2(acc[ii][0], acc[ii][1]);
        Pv[1] = make_ulonglong2(acc[ii][2], acc[ii][3]);
        Pv[2] = make_ulonglong2(acc[ii][4], acc[ii][5]);
        Pv[3] = make_ulonglong2(acc[ii][6], acc[ii][7]);
    }
}

// ---- helpers ----
__device__ __forceinline__ float4 quad_softmax(float q0, float q1, float q2, float q3) {
    float m = fmaxf(fmaxf(q0, q1), fmaxf(q2, q3));
    m = fmaxf(m, __shfl_xor_sync(0xffffffffu, m, 1));
    m = fmaxf(m, __shfl_xor_sync(0xffffffffu, m, 2));
    float e0 = expf(q0-m), e1 = expf(q1-m), e2 = expf(q2-m), e3 = expf(q3-m);
    float es = e0 + e1 + e2 + e3;
    es += __shfl_xor_sync(0xffffffffu, es, 1);
    es += __shfl_xor_sync(0xffffffffu, es, 2);
    float si = 1.0f / es;
    return make_float4(e0*si, e1*si, e2*si, e3*si);
}

__device__ __forceinline__ void grid_barrier(int tid, unsigned target) {
    __syncthreads();
    if (tid == 0) {
        __threadfence();
        atomicAdd(&g_bar, 1u);
        while (*(volatile unsigned*)&g_bar < target) { }
    }
    __syncthreads();
}

// ---- 3. mega: P-reduce -> U -> 5 mean-field iterations -> L, XOpart ----
__global__ void __launch_bounds__(512) mega_kernel(const float* __restrict__ X,
                                                   const float* __restrict__ wf,
                                                   const float* __restrict__ wc) {
    __shared__ float sX[RPB * DD];   // 32 KB
    __shared__ float ss[RPB * KK];   // 8 KB
    __shared__ float sG[DD * KK];    // 4 KB
    __shared__ float sM[KK * KK];
    __shared__ float cs[DD];
    int b = blockIdx.y, ch = blockIdx.x, tid = threadIdx.x;
    int lr = tid >> 2, q4 = tid & 3;
    size_t row = (size_t)b * NN + ch * RPB + lr;

    {   // stage X tile
        const float4* src = reinterpret_cast<const float4*>(X + ((size_t)b * NN + ch * RPB) * DD);
        float4* dst = reinterpret_cast<float4*>(sX);
#pragma unroll
        for (int e = tid; e < RPB * DD / 4; e += 512) dst[e] = src[e];
    }
    if (tid < 256) {                 // M = wf @ wc
        int k1 = tid >> 4, k2 = tid & 15;
        float mm = 0.f;
#pragma unroll
        for (int k = 0; k < KK; k++) mm += wf[k1*KK + k] * wc[k*KK + k2];
        sM[tid] = mm;
    }
    __syncthreads();

    // x slice in registers
    float x[16];
#pragma unroll
    for (int p = 0; p < 4; p++) {
        float4 v = *reinterpret_cast<const float4*>(&sX[lr * DD + q4 * 16 + p * 4]);
        x[4*p] = v.x; x[4*p+1] = v.y; x[4*p+2] = v.z; x[4*p+3] = v.w;
    }
    float nsq = 0.f;
#pragma unroll
    for (int d = 0; d < 16; d++) nsq += x[d] * x[d];
    nsq += __shfl_xor_sync(0xffffffffu, nsq, 1);
    nsq += __shfl_xor_sync(0xffffffffu, nsq, 2);

    if (tid < 64) {                  // colsum partial of this tile
        float s = 0.f;
#pragma unroll 8
        for (int i = 0; i < RPB; i++) s += sX[i * DD + tid];
        g_cspart[(b * GCH + ch) * DD + tid] = s;
    }

    // reduce P -> Uraw -> U (regs) -> s0
    float4 u4 = make_float4(0.f, 0.f, 0.f, 0.f);
#pragma unroll
    for (int jc = 0; jc < JC; jc++) {
        float4 p = __ldcg(reinterpret_cast<const float4*>(g_P + (row * JC + jc) * KK + q4 * 4));
        u4.x += p.x; u4.y += p.y; u4.z += p.z; u4.w += p.w;
    }
    float lsum = u4.x + u4.y + u4.z + u4.w;
    lsum += __shfl_xor_sync(0xffffffffu, lsum, 1);
    lsum += __shfl_xor_sync(0xffffffffu, lsum, 2);
    float inv = 1.0f / lsum;
    float uq0 = tanhf(u4.x * inv), uq1 = tanhf(u4.y * inv);
    float uq2 = tanhf(u4.z * inv), uq3 = tanhf(u4.w * inv);
    {
        float4 sv = quad_softmax(uq0, uq1, uq2, uq3);
        *reinterpret_cast<float4*>(&ss[lr * KK + q4 * 4]) = sv;
    }
    __syncthreads();

    {   // Gpart0
        int d = tid & 63, kb = (tid >> 6) * 2;
        float a0 = 0.f, a1 = 0.f;
#pragma unroll 4
        for (int i2 = 0; i2 < RPB; i2++) {
            float xx = sX[i2 * DD + d];
            a0 += xx * ss[i2 * KK + kb];
            a1 += xx * ss[i2 * KK + kb + 1];
        }
        float* gp = g_Gpart + (((size_t)b * GCH + ch) * DD + d) * KK + kb;
        gp[0] = a0; gp[1] = a1;
    }
    grid_barrier(tid, 1 * 128u);

    // colsum -> ninv
    if (tid < 64) {
        float s = 0.f;
#pragma unroll
        for (int c = 0; c < GCH; c++) s += __ldcg(&g_cspart[(b * GCH + c) * DD + tid]);
        cs[tid] = s;
    }
    __syncthreads();
    float dot = 0.f;
#pragma unroll
    for (int d = 0; d < 16; d++) dot += x[d] * cs[q4 * 16 + d];
    dot += __shfl_xor_sync(0xffffffffu, dot, 1);
    dot += __shfl_xor_sync(0xffffffffu, dot, 2);
    float ninv = 1.0f / (dot - nsq);

    unsigned phase = 1;
#pragma unroll 1
    for (int it = 0; it < ITERS; it++) {
        bool last = (it == ITERS - 1);
        if (tid < 256) {             // reduce Gpart
            float4 acc = make_float4(0.f, 0.f, 0.f, 0.f);
#pragma unroll
            for (int c2 = 0; c2 < GCH; c2++) {
                float4 p = __ldcg(reinterpret_cast<const float4*>(
                    g_Gpart + ((size_t)b * GCH + c2) * DD * KK + tid * 4));
                acc.x += p.x; acc.y += p.y; acc.z += p.z; acc.w += p.w;
            }
            *reinterpret_cast<float4*>(&sG[tid * 4]) = acc;
        }
        __syncthreads();

        float xg[KK];
#pragma unroll
        for (int k = 0; k < KK; k++) xg[k] = 0.f;
#pragma unroll
        for (int dd = 0; dd < 16; dd++) {
            float xd = x[dd];
            const float* g = &sG[(q4 * 16 + dd) * KK];
#pragma unroll
            for (int k = 0; k < KK; k++) xg[k] += xd * g[k];
        }
#pragma unroll
        for (int k = 0; k < KK; k++) {
            xg[k] += __shfl_xor_sync(0xffffffffu, xg[k], 1);
            xg[k] += __shfl_xor_sync(0xffffffffu, xg[k], 2);
        }

        float q0 = uq0, q1 = uq1, q2 = uq2, q3 = uq3;
#pragma unroll
        for (int k = 0; k < KK; k++) {
            float o = (xg[k] - nsq * ss[lr * KK + k]) * ninv;   // old s (pre-overwrite)
            const float* Mr = &sM[k * KK + q4 * 4];
            q0 -= o * Mr[0]; q1 -= o * Mr[1]; q2 -= o * Mr[2]; q3 -= o * Mr[3];
        }
        float4 sv = quad_softmax(q0, q1, q2, q3);
        __syncthreads();             // all old-ss reads complete
        *reinterpret_cast<float4*>(&ss[lr * KK + q4 * 4]) = sv;
        if (last) *reinterpret_cast<float4*>(g_s + row * KK + q4 * 4) = sv;
        __syncthreads();

        int d = tid & 63, kb = (tid >> 6) * 2;
        float a0 = 0.f, a1 = 0.f;
#pragma unroll 4
        for (int i2 = 0; i2 < RPB; i2++) {
            float xx = sX[i2 * DD + d];
            a0 += xx * ss[i2 * KK + kb];
            a1 += xx * ss[i2 * KK + kb + 1];
        }
        if (!last) {
            float* gp = g_Gpart + (((size_t)b * GCH + ch) * DD + d) * KK + kb;
            gp[0] = a0; gp[1] = a1;
            phase++;
            grid_barrier(tid, phase * 128u);
        } else {
            float* xp = g_XOpart + ((size_t)b * GCH + ch) * KK * DD;
            xp[(kb+0)*DD + d] = a0; xp[(kb+1)*DD + d] = a1;
        }
    }
}

// ---- 4. reduce t partials ----
__global__ void __launch_bounds__(256) reduceT_kernel() {
    size_t row = (size_t)blockIdx.x * 256 + threadIdx.x;
    float4 t0 = make_float4(0,0,0,0), t1 = t0, t2 = t0, t3 = t0;
#pragma unroll
    for (int jc = 0; jc < JC; jc++) {
        const float4* p = reinterpret_cast<const float4*>(g_P + (row * JC + jc) * KK);
        float4 a = p[0], bq = p[1], c = p[2], dd = p[3];
        t0.x += a.x; t0.y += a.y; t0.z += a.z; t0.w += a.w;
        t1.x += bq.x; t1.y += bq.y; t1.z += bq.z; t1.w += bq.w;
        t2.x += c.x; t2.y += c.y; t2.z += c.z; t2.w += c.w;
        t3.x += dd.x; t3.y += dd.y; t3.z += dd.z; t3.w += dd.w;
    }
    float4* t = reinterpret_cast<float4*>(g_t + row * KK);
    t[0] = t0; t[1] = t1; t[2] = t2; t[3] = t3;
}

// ---- 6. finalize ----
__global__ void __launch_bounds__(512) final_kernel(float* __restrict__ out) {
    __shared__ float sL[RPB * KK];
    __shared__ float sT[RPB * KK];
    __shared__ float sA[256];
    int b = blockIdx.x, tid = threadIdx.x;

    for (int e = tid; e < KK * DD; e += 512) {
        float s = 0.f;
#pragma unroll
        for (int ch = 0; ch < GCH; ch++)
            s += g_XOpart[((size_t)b * GCH + ch) * KK * DD + e];
        out[(size_t)b * KK * DD + e] = s;
    }

    int k1 = (tid >> 4) & 15, k2 = tid & 15, half = tid >> 8;
    float acc = 0.f;
    for (int ch = 0; ch < GCH; ch++) {
        const float4* Ls = reinterpret_cast<const float4*>(g_s + ((size_t)b * NN + ch * RPB) * KK);
        const float4* Ts = reinterpret_cast<const float4*>(g_t + ((size_t)b * NN + ch * RPB) * KK);
        reinterpret_cast<float4*>(sL)[tid] = Ls[tid];
        reinterpret_cast<float4*>(sT)[tid] = Ts[tid];
        __syncthreads();
        int i0 = half * 64;
#pragma unroll 8
        for (int i = 0; i < 64; i++)
            acc += sL[(i0 + i) * KK + k1] * sT[(i0 + i) * KK + k2];
        __syncthreads();
    }
    if (half == 1) sA[tid & 255] = acc;
    __syncthreads();
    if (half == 0)
        out[(size_t)BB * KK * DD + b * 256 + tid] = acc + sA[tid];
}

extern "C" void kernel_launch(void* const* d_in, const int* in_sizes, int n_in,
                              void* d_out, int out_size) {
    const float* X  = (const float*)d_in[0];
    const float* A  = (const float*)d_in[1];
    const float* wf = (const float*)d_in[2];
    const float* wc = (const float*)d_in[3];
    float* out = (float*)d_out;

    prep_kernel<<<BB*NN/128, 128>>>(X);
    bigpass3_kernel<0><<<dim3(NN/512, BB, JC), 128>>>(A);
    mega_kernel<<<dim3(GCH, BB), 512>>>(X, wf, wc);
    bigpass3_kernel<1><<<dim3(NN/512, BB, JC), 128>>>(A);
    reduceT_kernel<<<BB*NN/256, 256>>>();
    final_kernel<<<BB, 512>>>(out);
}

// round 5
// speedup vs baseline: 4.3387x; 1.0018x over previous
#include <cuda_runtime.h>
#include <cstdint>
#include <math.h>

// StructPool: B=8, N=2048, D=64, K=16, 5 mean-field iterations.

#define BB 8
#define NN 2048
#define DD 64
#define KK 16
#define ITERS 5
#define GCH 16          // 128-row chunks (= mega blocks per batch)
#define JC 32           // j-chunks for the A passes
#define JCH 64
#define RPB 128

// ---- scratch ----
__device__ float g_cspart[BB*GCH*DD];
__device__ float g_s[BB*NN*KK];                 // L at the end
__device__ float g_P[(size_t)BB*NN*JC*KK];      // [row][jc][16], 32 MB
__device__ float g_Gpart[BB*GCH*DD*KK];
__device__ float g_XOpart[BB*GCH*KK*DD];
__device__ float g_Apart[BB*8*KK*KK];
__device__ unsigned g_bar;

// ---- packed f32x2 ----
__device__ __forceinline__ unsigned long long pack2(float a) {
    unsigned long long r;
    asm("mov.b64 %0, {%1, %1};" : "=l"(r) : "f"(a));
    return r;
}
__device__ __forceinline__ unsigned long long fma2(unsigned long long a,
                                                   unsigned long long b,
                                                   unsigned long long c) {
    unsigned long long d;
    asm("fma.rn.f32x2 %0, %1, %2, %3;" : "=l"(d) : "l"(a), "l"(b), "l"(c));
    return d;
}

// ---- 1/3. A pass: P[row][jc][16] partials.
// MODE 0: V = pool(X) computed in-block (fused prep); also resets g_bar.
// MODE 1: V = g_s (L).
template <int MODE>
__global__ void __launch_bounds__(128) bigpass4_kernel(const float* __restrict__ A,
                                                       const float* __restrict__ X) {
    __shared__ float sV[JCH * KK];                  // 4 KB
    int b = blockIdx.y, jc = blockIdx.z;
    int i0 = blockIdx.x * 512 + threadIdx.x * 4;
    int j0 = jc * JCH;
    const float* Ab = A + (size_t)b * NN * NN;

    if (MODE == 0) {
        if (blockIdx.x == 0 && b == 0 && jc == 0 && threadIdx.x == 0) g_bar = 0u;
        int r2 = threadIdx.x >> 1, h = threadIdx.x & 1;
        const float4* xs = reinterpret_cast<const float4*>(
            X + ((size_t)b * NN + j0 + r2) * DD + h * 32);
        float* dst = &sV[r2 * KK + h * 8];
#pragma unroll
        for (int p = 0; p < 8; p++) {
            float4 v = xs[p];
            dst[p] = (v.x + v.y + v.z + v.w) * 0.25f;
        }
    } else {
        const float4* src = reinterpret_cast<const float4*>(g_s + ((size_t)b * NN + j0) * KK);
        float4* dst = reinterpret_cast<float4*>(sV);
#pragma unroll
        for (int e = threadIdx.x; e < JCH * KK / 4; e += 128) dst[e] = src[e];
    }
    __syncthreads();

    unsigned long long acc[4][8];
#pragma unroll
    for (int ii = 0; ii < 4; ii++)
#pragma unroll
        for (int p = 0; p < 8; p++) acc[ii][p] = 0ull;

#pragma unroll 4
    for (int j = 0; j < JCH; j++) {
        float4 a = __ldcs(reinterpret_cast<const float4*>(Ab + (size_t)(j0 + j) * NN + i0));
        unsigned long long aa0 = pack2(a.x), aa1 = pack2(a.y);
        unsigned long long aa2 = pack2(a.z), aa3 = pack2(a.w);
        const ulonglong2* vp = reinterpret_cast<const ulonglong2*>(sV + j * KK);
        ulonglong2 v0 = vp[0], v1 = vp[1], v2 = vp[2], v3 = vp[3];
        acc[0][0] = fma2(aa0, v0.x, acc[0][0]); acc[0][1] = fma2(aa0, v0.y, acc[0][1]);
        acc[0][2] = fma2(aa0, v1.x, acc[0][2]); acc[0][3] = fma2(aa0, v1.y, acc[0][3]);
        acc[0][4] = fma2(aa0, v2.x, acc[0][4]); acc[0][5] = fma2(aa0, v2.y, acc[0][5]);
        acc[0][6] = fma2(aa0, v3.x, acc[0][6]); acc[0][7] = fma2(aa0, v3.y, acc[0][7]);
        acc[1][0] = fma2(aa1, v0.x, acc[1][0]); acc[1][1] = fma2(aa1, v0.y, acc[1][1]);
        acc[1][2] = fma2(aa1, v1.x, acc[1][2]); acc[1][3] = fma2(aa1, v1.y, acc[1][3]);
        acc[1][4] = fma2(aa1, v2.x, acc[1][4]); acc[1][5] = fma2(aa1, v2.y, acc[1][5]);
        acc[1][6] = fma2(aa1, v3.x, acc[1][6]); acc[1][7] = fma2(aa1, v3.y, acc[1][7]);
        acc[2][0] = fma2(aa2, v0.x, acc[2][0]); acc[2][1] = fma2(aa2, v0.y, acc[2][1]);
        acc[2][2] = fma2(aa2, v1.x, acc[2][2]); acc[2][3] = fma2(aa2, v1.y, acc[2][3]);
        acc[2][4] = fma2(aa2, v2.x, acc[2][4]); acc[2][5] = fma2(aa2, v2.y, acc[2][5]);
        acc[2][6] = fma2(aa2, v3.x, acc[2][6]); acc[2][7] = fma2(aa2, v3.y, acc[2][7]);
        acc[3][0] = fma2(aa3, v0.x, acc[3][0]); acc[3][1] = fma2(aa3, v0.y, acc[3][1]);
        acc[3][2] = fma2(aa3, v1.x, acc[3][2]); acc[3][3] = fma2(aa3, v1.y, acc[3][3]);
        acc[3][4] = fma2(aa3, v2.x, acc[3][4]); acc[3][5] = fma2(aa3, v2.y, acc[3][5]);
        acc[3][6] = fma2(aa3, v3.x, acc[3][6]); acc[3][7] = fma2(aa3, v3.y, acc[3][7]);
    }

#pragma unroll
    for (int ii = 0; ii < 4; ii++) {
        float* P = g_P + (((size_t)b * NN + i0 + ii) * JC + jc) * KK;
        ulonglong2* Pv = reinterpret_cast<ulonglong2*>(P);
        Pv[0] = make_ulonglong2(acc[ii][0], acc[ii][1]);
        Pv[1] = make_ulonglong2(acc[ii][2], acc[ii][3]);
        Pv[2] = make_ulonglong2(acc[ii][4], acc[ii][5]);
        Pv[3] = make_ulonglong2(acc[ii][6], acc[ii][7]);
    }
}

// ---- helpers ----
__device__ __forceinline__ float4 quad_softmax(float q0, float q1, float q2, float q3) {
    float m = fmaxf(fmaxf(q0, q1), fmaxf(q2, q3));
    m = fmaxf(m, __shfl_xor_sync(0xffffffffu, m, 1));
    m = fmaxf(m, __shfl_xor_sync(0xffffffffu, m, 2));
    float e0 = expf(q0-m), e1 = expf(q1-m), e2 = expf(q2-m), e3 = expf(q3-m);
    float es = e0 + e1 + e2 + e3;
    es += __shfl_xor_sync(0xffffffffu, es, 1);
    es += __shfl_xor_sync(0xffffffffu, es, 2);
    float si = 1.0f / es;
    return make_float4(e0*si, e1*si, e2*si, e3*si);
}

__device__ __forceinline__ void grid_barrier(int tid, unsigned target) {
    __syncthreads();
    if (tid == 0) {
        __threadfence();
        atomicAdd(&g_bar, 1u);
        while (*(volatile unsigned*)&g_bar < target) { }
    }
    __syncthreads();
}

// ---- 2. mega: P-reduce -> U -> 5 mean-field iterations -> L, XOpart ----
__global__ void __launch_bounds__(512) mega_kernel(const float* __restrict__ X,
                                                   const float* __restrict__ wf,
                                                   const float* __restrict__ wc) {
    __shared__ float sX[RPB * DD];
    __shared__ float ss[RPB * KK];
    __shared__ float sG[DD * KK];
    __shared__ float sM[KK * KK];
    __shared__ float cs[DD];
    int b = blockIdx.y, ch = blockIdx.x, tid = threadIdx.x;
    int lr = tid >> 2, q4 = tid & 3;
    size_t row = (size_t)b * NN + ch * RPB + lr;

    {
        const float4* src = reinterpret_cast<const float4*>(X + ((size_t)b * NN + ch * RPB) * DD);
        float4* dst = reinterpret_cast<float4*>(sX);
#pragma unroll
        for (int e = tid; e < RPB * DD / 4; e += 512) dst[e] = src[e];
    }
    if (tid < 256) {
        int k1 = tid >> 4, k2 = tid & 15;
        float mm = 0.f;
#pragma unroll
        for (int k = 0; k < KK; k++) mm += wf[k1*KK + k] * wc[k*KK + k2];
        sM[tid] = mm;
    }
    __syncthreads();

    float x[16];
#pragma unroll
    for (int p = 0; p < 4; p++) {
        float4 v = *reinterpret_cast<const float4*>(&sX[lr * DD + q4 * 16 + p * 4]);
        x[4*p] = v.x; x[4*p+1] = v.y; x[4*p+2] = v.z; x[4*p+3] = v.w;
    }
    float nsq = 0.f;
#pragma unroll
    for (int d = 0; d < 16; d++) nsq += x[d] * x[d];
    nsq += __shfl_xor_sync(0xffffffffu, nsq, 1);
    nsq += __shfl_xor_sync(0xffffffffu, nsq, 2);

    if (tid < 64) {
        float s = 0.f;
#pragma unroll 8
        for (int i = 0; i < RPB; i++) s += sX[i * DD + tid];
        g_cspart[(b * GCH + ch) * DD + tid] = s;
    }

    float4 u4 = make_float4(0.f, 0.f, 0.f, 0.f);
#pragma unroll
    for (int jc = 0; jc < JC; jc++) {
        float4 p = __ldcg(reinterpret_cast<const float4*>(g_P + (row * JC + jc) * KK + q4 * 4));
        u4.x += p.x; u4.y += p.y; u4.z += p.z; u4.w += p.w;
    }
    float lsum = u4.x + u4.y + u4.z + u4.w;
    lsum += __shfl_xor_sync(0xffffffffu, lsum, 1);
    lsum += __shfl_xor_sync(0xffffffffu, lsum, 2);
    float inv = 1.0f / lsum;
    float uq0 = tanhf(u4.x * inv), uq1 = tanhf(u4.y * inv);
    float uq2 = tanhf(u4.z * inv), uq3 = tanhf(u4.w * inv);
    {
        float4 sv = quad_softmax(uq0, uq1, uq2, uq3);
        *reinterpret_cast<float4*>(&ss[lr * KK + q4 * 4]) = sv;
    }
    __syncthreads();

    {
        int d = tid & 63, kb = (tid >> 6) * 2;
        float a0 = 0.f, a1 = 0.f;
#pragma unroll 4
        for (int i2 = 0; i2 < RPB; i2++) {
            float xx = sX[i2 * DD + d];
            a0 += xx * ss[i2 * KK + kb];
            a1 += xx * ss[i2 * KK + kb + 1];
        }
        float* gp = g_Gpart + (((size_t)b * GCH + ch) * DD + d) * KK + kb;
        gp[0] = a0; gp[1] = a1;
    }
    grid_barrier(tid, 1 * 128u);

    if (tid < 64) {
        float s = 0.f;
#pragma unroll
        for (int c = 0; c < GCH; c++) s += __ldcg(&g_cspart[(b * GCH + c) * DD + tid]);
        cs[tid] = s;
    }
    __syncthreads();
    float dot = 0.f;
#pragma unroll
    for (int d = 0; d < 16; d++) dot += x[d] * cs[q4 * 16 + d];
    dot += __shfl_xor_sync(0xffffffffu, dot, 1);
    dot += __shfl_xor_sync(0xffffffffu, dot, 2);
    float ninv = 1.0f / (dot - nsq);

    unsigned phase = 1;
#pragma unroll 1
    for (int it = 0; it < ITERS; it++) {
        bool last = (it == ITERS - 1);
        if (tid < 256) {
            float4 acc = make_float4(0.f, 0.f, 0.f, 0.f);
#pragma unroll
            for (int c2 = 0; c2 < GCH; c2++) {
                float4 p = __ldcg(reinterpret_cast<const float4*>(
                    g_Gpart + ((size_t)b * GCH + c2) * DD * KK + tid * 4));
                acc.x += p.x; acc.y += p.y; acc.z += p.z; acc.w += p.w;
            }
            *reinterpret_cast<float4*>(&sG[tid * 4]) = acc;
        }
        __syncthreads();

        float xg[KK];
#pragma unroll
        for (int k = 0; k < KK; k++) xg[k] = 0.f;
#pragma unroll
        for (int dd = 0; dd < 16; dd++) {
            float xd = x[dd];
            const float* g = &sG[(q4 * 16 + dd) * KK];
#pragma unroll
            for (int k = 0; k < KK; k++) xg[k] += xd * g[k];
        }
#pragma unroll
        for (int k = 0; k < KK; k++) {
            xg[k] += __shfl_xor_sync(0xffffffffu, xg[k], 1);
            xg[k] += __shfl_xor_sync(0xffffffffu, xg[k], 2);
        }

        float q0 = uq0, q1 = uq1, q2 = uq2, q3 = uq3;
#pragma unroll
        for (int k = 0; k < KK; k++) {
            float o = (xg[k] - nsq * ss[lr * KK + k]) * ninv;
            const float* Mr = &sM[k * KK + q4 * 4];
            q0 -= o * Mr[0]; q1 -= o * Mr[1]; q2 -= o * Mr[2]; q3 -= o * Mr[3];
        }
        float4 sv = quad_softmax(q0, q1, q2, q3);
        __syncthreads();
        *reinterpret_cast<float4*>(&ss[lr * KK + q4 * 4]) = sv;
        if (last) *reinterpret_cast<float4*>(g_s + row * KK + q4 * 4) = sv;
        __syncthreads();

        int d = tid & 63, kb = (tid >> 6) * 2;
        float a0 = 0.f, a1 = 0.f;
#pragma unroll 4
        for (int i2 = 0; i2 < RPB; i2++) {
            float xx = sX[i2 * DD + d];
            a0 += xx * ss[i2 * KK + kb];
            a1 += xx * ss[i2 * KK + kb + 1];
        }
        if (!last) {
            float* gp = g_Gpart + (((size_t)b * GCH + ch) * DD + d) * KK + kb;
            gp[0] = a0; gp[1] = a1;
            phase++;
            grid_barrier(tid, phase * 128u);
        } else {
            float* xp = g_XOpart + ((size_t)b * GCH + ch) * KK * DD;
            xp[(kb+0)*DD + d] = a0; xp[(kb+1)*DD + d] = a1;
        }
    }
}

// ---- 4. finalT: t = reduce(P) per row; partial A_out = L^T t per 256-row chunk ----
__global__ void __launch_bounds__(256) finalT_kernel() {
    __shared__ float sT[256 * KK];   // 16 KB
    __shared__ float sL[256 * KK];   // 16 KB
    int ch = blockIdx.x, b = blockIdx.y, tid = threadIdx.x;
    size_t row = (size_t)b * NN + ch * 256 + tid;

    float4 t0 = make_float4(0,0,0,0), t1 = t0, t2 = t0, t3 = t0;
#pragma unroll 4
    for (int jc = 0; jc < JC; jc++) {
        const float4* p = reinterpret_cast<const float4*>(g_P + (row * JC + jc) * KK);
        float4 a = p[0], bq = p[1], c = p[2], dd = p[3];
        t0.x += a.x; t0.y += a.y; t0.z += a.z; t0.w += a.w;
        t1.x += bq.x; t1.y += bq.y; t1.z += bq.z; t1.w += bq.w;
        t2.x += c.x; t2.y += c.y; t2.z += c.z; t2.w += c.w;
        t3.x += dd.x; t3.y += dd.y; t3.z += dd.z; t3.w += dd.w;
    }
    float4* ts = reinterpret_cast<float4*>(&sT[tid * KK]);
    ts[0] = t0; ts[1] = t1; ts[2] = t2; ts[3] = t3;
    {
        const float4* Ls = reinterpret_cast<const float4*>(g_s + row * KK);
        float4* ld = reinterpret_cast<float4*>(&sL[tid * KK]);
        ld[0] = Ls[0]; ld[1] = Ls[1]; ld[2] = Ls[2]; ld[3] = Ls[3];
    }
    __syncthreads();

    int k1 = tid >> 4, k2 = tid & 15;
    float acc = 0.f;
#pragma unroll 8
    for (int i = 0; i < 256; i++)
        acc += sL[i * KK + k1] * sT[i * KK + k2];
    g_Apart[((size_t)b * 8 + ch) * 256 + tid] = acc;
}

// ---- 5. final: reduce XOpart -> X_out, reduce Apart -> A_out ----
__global__ void __launch_bounds__(256) final_kernel(float* __restrict__ out) {
    int b = blockIdx.x, tid = threadIdx.x;
    for (int e = tid; e < KK * DD; e += 256) {
        float s = 0.f;
#pragma unroll
        for (int ch = 0; ch < GCH; ch++)
            s += g_XOpart[((size_t)b * GCH + ch) * KK * DD + e];
        out[(size_t)b * KK * DD + e] = s;
    }
    float s = 0.f;
#pragma unroll
    for (int ch = 0; ch < 8; ch++)
        s += g_Apart[((size_t)b * 8 + ch) * 256 + tid];
    out[(size_t)BB * KK * DD + b * 256 + tid] = s;
}

extern "C" void kernel_launch(void* const* d_in, const int* in_sizes, int n_in,
                              void* d_out, int out_size) {
    const float* X  = (const float*)d_in[0];
    const float* A  = (const float*)d_in[1];
    const float* wf = (const float*)d_in[2];
    const float* wc = (const float*)d_in[3];
    float* out = (float*)d_out;

    bigpass4_kernel<0><<<dim3(NN/512, BB, JC), 128>>>(A, X);
    mega_kernel<<<dim3(GCH, BB), 512>>>(X, wf, wc);
    bigpass4_kernel<1><<<dim3(NN/512, BB, JC), 128>>>(A, X);
    finalT_kernel<<<dim3(8, BB), 256>>>();
    final_kernel<<<BB, 256>>>(out);
}